// round 6
// baseline (speedup 1.0000x reference)
#include <cuda_runtime.h>
#include <math.h>

#define NQ    8192
#define ND    32768
#define DK    512
#define TOPK  20
#define THRESH 5e-5f

// 1 GiB scratch for the full similarity matrix [NQ, ND]
__device__ float g_sims[(size_t)NQ * (size_t)ND];

// ---------------------------------------------------------------------------
// Kernel A: fp32 SGEMM, C = Q @ D^T   (NT layout: both K-contiguous)
// BM=BN=128, BK=16, 256 threads, 8x8 accumulators per thread.
// ---------------------------------------------------------------------------
#define BM 128
#define BN 128
#define BK 16
#define TM 8
#define TN 8
#define AS_LD (BM + 4)

__global__ __launch_bounds__(256)
void sgemm_nt_kernel(const float* __restrict__ Q, const float* __restrict__ D)
{
    __shared__ float As[BK][AS_LD];
    __shared__ float Bs[BK][AS_LD];

    const int bx  = blockIdx.x;   // N tile
    const int by  = blockIdx.y;   // M tile
    const int tid = threadIdx.x;
    const int tx  = tid & 15;     // 0..15  -> N sub-tile
    const int ty  = tid >> 4;     // 0..15  -> M sub-tile

    const float* Qb = Q + (size_t)by * BM * DK;
    const float* Db = D + (size_t)bx * BN * DK;

    float acc[TM][TN];
#pragma unroll
    for (int i = 0; i < TM; i++)
#pragma unroll
        for (int j = 0; j < TN; j++)
            acc[i][j] = 0.0f;

    for (int k0 = 0; k0 < DK; k0 += BK) {
        // Load A and B tiles: 128 rows x 16 k-cols = 512 float4 each.
        // s = l*256 + tid -> 4 consecutive threads cover 64 contiguous bytes
        // of one row (full 32B-sector utilization).
#pragma unroll
        for (int l = 0; l < 2; l++) {
            int s   = l * 256 + tid;      // 0..511
            int row = s >> 2;             // 0..127
            int c4  = (s & 3) * 4;        // 0,4,8,12

            float4 va = *(const float4*)(Qb + (size_t)row * DK + k0 + c4);
            As[c4 + 0][row] = va.x;
            As[c4 + 1][row] = va.y;
            As[c4 + 2][row] = va.z;
            As[c4 + 3][row] = va.w;

            float4 vb = *(const float4*)(Db + (size_t)row * DK + k0 + c4);
            Bs[c4 + 0][row] = vb.x;
            Bs[c4 + 1][row] = vb.y;
            Bs[c4 + 2][row] = vb.z;
            Bs[c4 + 3][row] = vb.w;
        }
        __syncthreads();

#pragma unroll
        for (int k = 0; k < BK; k++) {
            float a[TM], b[TN];
            *(float4*)&a[0] = *(const float4*)&As[k][ty * TM];
            *(float4*)&a[4] = *(const float4*)&As[k][ty * TM + 4];
            *(float4*)&b[0] = *(const float4*)&Bs[k][tx * TN];
            *(float4*)&b[4] = *(const float4*)&Bs[k][tx * TN + 4];
#pragma unroll
            for (int i = 0; i < TM; i++)
#pragma unroll
                for (int j = 0; j < TN; j++)
                    acc[i][j] = fmaf(a[i], b[j], acc[i][j]);
        }
        __syncthreads();
    }

    // Write the 128x128 output tile (float4 stores)
    float* Cb = g_sims + (size_t)(by * BM) * ND + (size_t)bx * BN;
#pragma unroll
    for (int i = 0; i < TM; i++) {
        int row = ty * TM + i;
        float* cr = Cb + (size_t)row * ND + tx * TN;
        float4 v0 = make_float4(acc[i][0], acc[i][1], acc[i][2], acc[i][3]);
        float4 v1 = make_float4(acc[i][4], acc[i][5], acc[i][6], acc[i][7]);
        *(float4*)(cr + 0) = v0;
        *(float4*)(cr + 4) = v1;
    }
}

// ---------------------------------------------------------------------------
// Kernel B: per-row softmax stats + top-20 selection.
// One block (256 threads) per query row; row staged in 128KB dynamic smem.
// ---------------------------------------------------------------------------
__global__ __launch_bounds__(256)
void topk_kernel(float* __restrict__ out_scores,
                 float* __restrict__ out_inds,
                 float* __restrict__ out_n,
                 float* __restrict__ out_mask)
{
    extern __shared__ float row[];           // ND floats
    __shared__ float redv[256];
    __shared__ int   redi[256];
    __shared__ float topv[TOPK];
    __shared__ int   topi[TOPK];
    __shared__ float s_max, s_sum;

    const int r   = blockIdx.x;
    const int tid = threadIdx.x;

    const float4* src  = (const float4*)(g_sims + (size_t)r * ND);
    float4*       drow = (float4*)row;

    // Load row into smem + local max
    float lmax = -INFINITY;
    for (int i = tid; i < ND / 4; i += 256) {
        float4 v = src[i];
        drow[i] = v;
        lmax = fmaxf(lmax, fmaxf(fmaxf(v.x, v.y), fmaxf(v.z, v.w)));
    }
    redv[tid] = lmax;
    __syncthreads();
#pragma unroll
    for (int s = 128; s > 0; s >>= 1) {
        if (tid < s) redv[tid] = fmaxf(redv[tid], redv[tid + s]);
        __syncthreads();
    }
    if (tid == 0) s_max = redv[0];
    __syncthreads();
    const float m = s_max;

    // Sum of exp(v - max)
    float lsum = 0.0f;
    for (int i = tid; i < ND / 4; i += 256) {
        float4 v = drow[i];
        lsum += expf(v.x - m) + expf(v.y - m) + expf(v.z - m) + expf(v.w - m);
    }
    redv[tid] = lsum;
    __syncthreads();
#pragma unroll
    for (int s = 128; s > 0; s >>= 1) {
        if (tid < s) redv[tid] += redv[tid + s];
        __syncthreads();
    }
    if (tid == 0) s_sum = redv[0];
    __syncthreads();
    const float sum = s_sum;

    // 20 iterations of block-wide argmax (tie-break: lowest index, matching
    // jax.lax.top_k first-occurrence ordering). Winner slot -> -INF.
    for (int it = 0; it < TOPK; it++) {
        float bv = -INFINITY;
        int   bi = ND;
        for (int i = tid; i < ND / 4; i += 256) {
            float4 v  = drow[i];
            int base  = i * 4;
            if (v.x > bv) { bv = v.x; bi = base; }
            if (v.y > bv) { bv = v.y; bi = base + 1; }
            if (v.z > bv) { bv = v.z; bi = base + 2; }
            if (v.w > bv) { bv = v.w; bi = base + 3; }
        }
        redv[tid] = bv;
        redi[tid] = bi;
        __syncthreads();
#pragma unroll
        for (int s = 128; s > 0; s >>= 1) {
            if (tid < s) {
                float ov = redv[tid + s];
                int   oi = redi[tid + s];
                if (ov > redv[tid] || (ov == redv[tid] && oi < redi[tid])) {
                    redv[tid] = ov;
                    redi[tid] = oi;
                }
            }
            __syncthreads();
        }
        if (tid == 0) {
            topv[it] = redv[0];
            topi[it] = redi[0];
            row[redi[0]] = -INFINITY;
        }
        __syncthreads();
    }

    // Emit outputs
    if (tid < TOPK) {
        float sc   = expf(topv[tid] - m) / sum;
        bool  keep = sc > THRESH;
        out_scores[(size_t)r * TOPK + tid] = keep ? sc : 0.0f;
        out_inds  [(size_t)r * TOPK + tid] = (float)topi[tid];
        out_mask  [(size_t)r * TOPK + tid] = keep ? 1.0f : 0.0f;
    }
    if (tid == 0) {
        int cnt = 0;
#pragma unroll
        for (int j = 0; j < TOPK; j++) {
            float sc = expf(topv[j] - m) / sum;
            cnt += (sc > THRESH) ? 1 : 0;
        }
        out_n[r] = (float)cnt;
    }
}

// ---------------------------------------------------------------------------
extern "C" void kernel_launch(void* const* d_in, const int* in_sizes, int n_in,
                              void* d_out, int out_size)
{
    const float* Q = (const float*)d_in[0];
    const float* D = (const float*)d_in[1];
    float* out = (float*)d_out;

    // Output layout (flattened, f32): scores[NQ*K], inds[NQ*K], n[NQ], mask[NQ*K]
    float* out_scores = out;
    float* out_inds   = out + (size_t)NQ * TOPK;
    float* out_n      = out + (size_t)2 * NQ * TOPK;
    float* out_mask   = out + (size_t)2 * NQ * TOPK + NQ;

    // Opt-in to 128KB dynamic smem for the topk kernel (idempotent, not a
    // stream op -> graph-capture safe).
    cudaFuncSetAttribute(topk_kernel,
                         cudaFuncAttributeMaxDynamicSharedMemorySize,
                         ND * (int)sizeof(float));

    dim3 g1(ND / BN, NQ / BM);   // (256, 64)
    sgemm_nt_kernel<<<g1, 256>>>(Q, D);

    topk_kernel<<<NQ, 256, ND * sizeof(float)>>>(out_scores, out_inds, out_n, out_mask);

    (void)in_sizes; (void)n_in; (void)out_size;
}

// round 14
// speedup vs baseline: 1.0044x; 1.0044x over previous
#include <cuda_runtime.h>
#include <math.h>
#include <stdint.h>

#define NQ    8192
#define ND    32768
#define DK    512
#define TOPK  20
#define THRESH 5e-5f

// 1 GiB scratch for the full similarity matrix [NQ, ND]
__device__ float g_sims[(size_t)NQ * (size_t)ND];

// ---------------------------------------------------------------------------
// Packed fp32x2 helpers (PTX 8.6+, sm_100-family base ISA).
// Each lane of fma.rn.f32x2 is an independent IEEE fma.rn.f32 -> per-output
// rounding sequence is bitwise identical to scalar fmaf chains.
// ---------------------------------------------------------------------------
__device__ __forceinline__ unsigned long long dup2(float x) {
    unsigned long long r; unsigned int u = __float_as_uint(x);
    asm("mov.b64 %0, {%1, %1};" : "=l"(r) : "r"(u));
    return r;
}
__device__ __forceinline__ void fma2(unsigned long long& c,
                                     unsigned long long a, unsigned long long b) {
    asm("fma.rn.f32x2 %0, %1, %2, %0;" : "+l"(c) : "l"(a), "l"(b));
}
__device__ __forceinline__ float2 unp2(unsigned long long v) {
    unsigned int lo, hi;
    asm("mov.b64 {%0, %1}, %2;" : "=r"(lo), "=r"(hi) : "l"(v));
    return make_float2(__uint_as_float(lo), __uint_as_float(hi));
}

// ---------------------------------------------------------------------------
// Kernel A: fp32x2 SGEMM, C = Q @ D^T. Serial ascending-k fma per output
// (bitwise-matches the reference's fp32 GEMM rounding).
// BM=128, BN=256, BK=16, 256 threads, per-thread 8(M) x 16(N) outputs held as
// 8x8 packed f32x2 accumulators (pairs across N).
// Bs layout: groups of 16 floats + 4 pad -> 64B-stride reads are conflict-free.
// ---------------------------------------------------------------------------
#define BM  128
#define BN2 256
#define BK  16
#define BS_ROW 320                       // 16 groups * (16 data + 4 pad)
#define BOFF(c) ((((c) >> 4) * 20) + ((c) & 15))

__global__ __launch_bounds__(256, 1)
void sgemm2_kernel(const float* __restrict__ Q, const float* __restrict__ D)
{
    __shared__ float As[BK][BM + 4];
    __shared__ float Bs[BK][BS_ROW];

    const int tid = threadIdx.x;
    const int tx  = tid & 15;            // N sub-tile: cols tx*16 .. tx*16+15
    const int ty  = tid >> 4;            // M sub-tile: rows ty*8 .. ty*8+7

    // L2-friendly raster: groups of 8 M-tiles, N-major inside (D stays L2-resident)
    const int NX = ND / BN2;             // 128
    int bid   = blockIdx.x;
    int group = bid / (8 * NX);
    int rem   = bid - group * (8 * NX);
    int bx    = rem >> 3;                // N tile
    int by    = group * 8 + (rem & 7);   // M tile

    const float* Qb = Q + (size_t)by * BM * DK;
    const float* Db = D + (size_t)bx * BN2 * DK;

    unsigned long long acc[8][8];
#pragma unroll
    for (int i = 0; i < 8; i++)
#pragma unroll
        for (int j = 0; j < 8; j++) acc[i][j] = 0ull;

    for (int k0 = 0; k0 < DK; k0 += BK) {
        // As: 128 rows x 16 k = 512 float4; 2 per thread. 4 consecutive threads
        // cover 64 contiguous bytes of one Q row (full sector utilization).
#pragma unroll
        for (int l = 0; l < 2; l++) {
            int s = l * 256 + tid;
            int row = s >> 2, c4 = (s & 3) * 4;
            float4 va = *(const float4*)(Qb + (size_t)row * DK + k0 + c4);
            As[c4 + 0][row] = va.x;
            As[c4 + 1][row] = va.y;
            As[c4 + 2][row] = va.z;
            As[c4 + 3][row] = va.w;
        }
        // Bs: 256 rows x 16 k = 1024 float4; 4 per thread; padded group layout.
#pragma unroll
        for (int l = 0; l < 4; l++) {
            int s = l * 256 + tid;
            int row = s >> 2, c4 = (s & 3) * 4;
            float4 vb = *(const float4*)(Db + (size_t)row * DK + k0 + c4);
            int o = BOFF(row);
            Bs[c4 + 0][o] = vb.x;
            Bs[c4 + 1][o] = vb.y;
            Bs[c4 + 2][o] = vb.z;
            Bs[c4 + 3][o] = vb.w;
        }
        __syncthreads();

#pragma unroll
        for (int k = 0; k < BK; k++) {
            float4 a0 = *(const float4*)&As[k][ty * 8];
            float4 a1 = *(const float4*)&As[k][ty * 8 + 4];
            // 16 B-floats = 8 packed f32x2 lanes, direct 16B loads (conflict-free)
            ulonglong2 b0 = *(const ulonglong2*)&Bs[k][tx * 20];
            ulonglong2 b1 = *(const ulonglong2*)&Bs[k][tx * 20 + 4];
            ulonglong2 b2 = *(const ulonglong2*)&Bs[k][tx * 20 + 8];
            ulonglong2 b3 = *(const ulonglong2*)&Bs[k][tx * 20 + 12];
            unsigned long long bp[8] = {b0.x, b0.y, b1.x, b1.y, b2.x, b2.y, b3.x, b3.y};
            float av[8] = {a0.x, a0.y, a0.z, a0.w, a1.x, a1.y, a1.z, a1.w};
#pragma unroll
            for (int i = 0; i < 8; i++) {
                unsigned long long ad = dup2(av[i]);
#pragma unroll
                for (int j = 0; j < 8; j++) fma2(acc[i][j], ad, bp[j]);
            }
        }
        __syncthreads();
    }

    // Epilogue: coalesced float4 stores (16 threads x 64B = 1KB contiguous)
    float* Cb = g_sims + ((size_t)by * BM + ty * 8) * ND + (size_t)bx * BN2 + tx * 16;
#pragma unroll
    for (int i = 0; i < 8; i++) {
        float* cr = Cb + (size_t)i * ND;
#pragma unroll
        for (int jj = 0; jj < 4; jj++) {
            float2 p = unp2(acc[i][2 * jj]);
            float2 q = unp2(acc[i][2 * jj + 1]);
            *(float4*)(cr + jj * 4) = make_float4(p.x, p.y, q.x, q.y);
        }
    }
}

// ---------------------------------------------------------------------------
// Kernel B: per-row softmax stats + top-20 selection (round-6 known-correct).
// ---------------------------------------------------------------------------
__global__ __launch_bounds__(256)
void topk_kernel(float* __restrict__ out_scores,
                 float* __restrict__ out_inds,
                 float* __restrict__ out_n,
                 float* __restrict__ out_mask)
{
    extern __shared__ float row[];           // ND floats
    __shared__ float redv[256];
    __shared__ int   redi[256];
    __shared__ float topv[TOPK];
    __shared__ int   topi[TOPK];
    __shared__ float s_max, s_sum;

    const int r   = blockIdx.x;
    const int tid = threadIdx.x;

    const float4* src  = (const float4*)(g_sims + (size_t)r * ND);
    float4*       drow = (float4*)row;

    float lmax = -INFINITY;
    for (int i = tid; i < ND / 4; i += 256) {
        float4 v = src[i];
        drow[i] = v;
        lmax = fmaxf(lmax, fmaxf(fmaxf(v.x, v.y), fmaxf(v.z, v.w)));
    }
    redv[tid] = lmax;
    __syncthreads();
#pragma unroll
    for (int s = 128; s > 0; s >>= 1) {
        if (tid < s) redv[tid] = fmaxf(redv[tid], redv[tid + s]);
        __syncthreads();
    }
    if (tid == 0) s_max = redv[0];
    __syncthreads();
    const float m = s_max;

    float lsum = 0.0f;
    for (int i = tid; i < ND / 4; i += 256) {
        float4 v = drow[i];
        lsum += expf(v.x - m) + expf(v.y - m) + expf(v.z - m) + expf(v.w - m);
    }
    redv[tid] = lsum;
    __syncthreads();
#pragma unroll
    for (int s = 128; s > 0; s >>= 1) {
        if (tid < s) redv[tid] += redv[tid + s];
        __syncthreads();
    }
    if (tid == 0) s_sum = redv[0];
    __syncthreads();
    const float sum = s_sum;

    for (int it = 0; it < TOPK; it++) {
        float bv = -INFINITY;
        int   bi = ND;
        for (int i = tid; i < ND / 4; i += 256) {
            float4 v  = drow[i];
            int base  = i * 4;
            if (v.x > bv) { bv = v.x; bi = base; }
            if (v.y > bv) { bv = v.y; bi = base + 1; }
            if (v.z > bv) { bv = v.z; bi = base + 2; }
            if (v.w > bv) { bv = v.w; bi = base + 3; }
        }
        redv[tid] = bv;
        redi[tid] = bi;
        __syncthreads();
#pragma unroll
        for (int s = 128; s > 0; s >>= 1) {
            if (tid < s) {
                float ov = redv[tid + s];
                int   oi = redi[tid + s];
                if (ov > redv[tid] || (ov == redv[tid] && oi < redi[tid])) {
                    redv[tid] = ov;
                    redi[tid] = oi;
                }
            }
            __syncthreads();
        }
        if (tid == 0) {
            topv[it] = redv[0];
            topi[it] = redi[0];
            row[redi[0]] = -INFINITY;
        }
        __syncthreads();
    }

    if (tid < TOPK) {
        float sc   = expf(topv[tid] - m) / sum;
        bool  keep = sc > THRESH;
        out_scores[(size_t)r * TOPK + tid] = keep ? sc : 0.0f;
        out_inds  [(size_t)r * TOPK + tid] = (float)topi[tid];
        out_mask  [(size_t)r * TOPK + tid] = keep ? 1.0f : 0.0f;
    }
    if (tid == 0) {
        int cnt = 0;
#pragma unroll
        for (int j = 0; j < TOPK; j++) {
            float sc = expf(topv[j] - m) / sum;
            cnt += (sc > THRESH) ? 1 : 0;
        }
        out_n[r] = (float)cnt;
    }
}

// ---------------------------------------------------------------------------
extern "C" void kernel_launch(void* const* d_in, const int* in_sizes, int n_in,
                              void* d_out, int out_size)
{
    const float* Q = (const float*)d_in[0];
    const float* D = (const float*)d_in[1];
    float* out = (float*)d_out;

    float* out_scores = out;
    float* out_inds   = out + (size_t)NQ * TOPK;
    float* out_n      = out + (size_t)2 * NQ * TOPK;
    float* out_mask   = out + (size_t)2 * NQ * TOPK + NQ;

    cudaFuncSetAttribute(topk_kernel,
                         cudaFuncAttributeMaxDynamicSharedMemorySize,
                         ND * (int)sizeof(float));

    sgemm2_kernel<<<(NQ / BM) * (ND / BN2), 256>>>(Q, D);

    topk_kernel<<<NQ, 256, ND * sizeof(float)>>>(out_scores, out_inds, out_n, out_mask);

    (void)in_sizes; (void)n_in; (void)out_size;
}

// round 17
// speedup vs baseline: 1.1049x; 1.1001x over previous
#include <cuda_runtime.h>
#include <cuda_bf16.h>
#include <math.h>
#include <stdint.h>

#define NQ    8192
#define ND    32768
#define DK    512
#define TOPK  20
#define THRESH 5e-5f
#define CANDCAP 2048

// Scratch
__device__ float g_sims[(size_t)NQ * (size_t)ND];
__device__ __nv_bfloat16 g_Qh[(size_t)NQ * DK], g_Qm[(size_t)NQ * DK], g_Ql[(size_t)NQ * DK];
__device__ __nv_bfloat16 g_Dh[(size_t)ND * DK], g_Dm[(size_t)ND * DK], g_Dl[(size_t)ND * DK];
__device__ float g_rowm[NQ], g_rowsum[NQ];
__device__ int   g_cand[(size_t)NQ * CANDCAP];
__device__ int   g_ncand[NQ];

// ---------------------------------------------------------------------------
// sm_80-generic PTX helpers
// ---------------------------------------------------------------------------
__device__ __forceinline__ uint32_t smem_u32(const void* p) {
    uint32_t a;
    asm("{ .reg .u64 t; cvta.to.shared.u64 t, %1; cvt.u32.u64 %0, t; }" : "=r"(a) : "l"(p));
    return a;
}
__device__ __forceinline__ void cp16(uint32_t dst, const void* src) {
    asm volatile("cp.async.cg.shared.global [%0], [%1], 16;" :: "r"(dst), "l"(src));
}
#define CP_COMMIT() asm volatile("cp.async.commit_group;" ::: "memory")
#define CP_WAIT2()  asm volatile("cp.async.wait_group 2;" ::: "memory")

__device__ __forceinline__ void ldsm4(uint32_t* r, uint32_t addr) {
    asm volatile("ldmatrix.sync.aligned.m8n8.x4.shared.b16 {%0,%1,%2,%3}, [%4];"
        : "=r"(r[0]), "=r"(r[1]), "=r"(r[2]), "=r"(r[3]) : "r"(addr));
}
__device__ __forceinline__ void mma16816(float* c, const uint32_t* a, uint32_t b0, uint32_t b1) {
    asm volatile("mma.sync.aligned.m16n8k16.row.col.f32.bf16.bf16.f32 "
        "{%0,%1,%2,%3}, {%4,%5,%6,%7}, {%8,%9}, {%0,%1,%2,%3};"
        : "+f"(c[0]), "+f"(c[1]), "+f"(c[2]), "+f"(c[3])
        : "r"(a[0]), "r"(a[1]), "r"(a[2]), "r"(a[3]), "r"(b0), "r"(b1));
}

// ---------------------------------------------------------------------------
// bf16x3 split: x = h + m + l
// ---------------------------------------------------------------------------
__device__ __forceinline__ void split3(float x, __nv_bfloat16& h, __nv_bfloat16& m, __nv_bfloat16& l) {
    h = __float2bfloat16(x);      float r = x - __bfloat162float(h);
    m = __float2bfloat16(r);      r -= __bfloat162float(m);
    l = __float2bfloat16(r);
}
__global__ __launch_bounds__(256) void split_q(const float* __restrict__ x) {
    int i = blockIdx.x * 256 + threadIdx.x;
    if (i >= NQ * DK / 2) return;
    float2 v = ((const float2*)x)[i];
    __nv_bfloat16 h0, m0, l0, h1, m1, l1;
    split3(v.x, h0, m0, l0);
    split3(v.y, h1, m1, l1);
    ((__nv_bfloat162*)g_Qh)[i] = __halves2bfloat162(h0, h1);
    ((__nv_bfloat162*)g_Qm)[i] = __halves2bfloat162(m0, m1);
    ((__nv_bfloat162*)g_Ql)[i] = __halves2bfloat162(l0, l1);
}
__global__ __launch_bounds__(256) void split_d(const float* __restrict__ x) {
    int i = blockIdx.x * 256 + threadIdx.x;
    if (i >= ND * DK / 2) return;
    float2 v = ((const float2*)x)[i];
    __nv_bfloat16 h0, m0, l0, h1, m1, l1;
    split3(v.x, h0, m0, l0);
    split3(v.y, h1, m1, l1);
    ((__nv_bfloat162*)g_Dh)[i] = __halves2bfloat162(h0, h1);
    ((__nv_bfloat162*)g_Dm)[i] = __halves2bfloat162(m0, m1);
    ((__nv_bfloat162*)g_Dl)[i] = __halves2bfloat162(l0, l1);
}

// ---------------------------------------------------------------------------
// HMMA bf16x6 GEMM (round-12/16, functionally verified)
// ---------------------------------------------------------------------------
#define T_PITCH 80
#define TILE_B  (128 * T_PITCH)
#define STAGE_B (6 * TILE_B)
#define GEMM_SMEM (3 * STAGE_B)
#define NCHUNK (DK / 32)

__global__ __launch_bounds__(256, 1) void gemm_kernel() {
    extern __shared__ char smem[];
    const uint32_t sb = smem_u32(smem);
    const int tid  = threadIdx.x;
    const int wid  = tid >> 5, lane = tid & 31;
    const int wm   = wid & 1;
    const int wn   = wid >> 1;

    const int NX = ND / 128;
    int bid   = blockIdx.x;
    int group = bid / (8 * NX);
    int rem   = bid - group * (8 * NX);
    int bx    = rem >> 3;
    int by    = group * 8 + (rem & 7);

    const char* base[6];
    {
        size_t qo = (size_t)by * 128 * DK * 2;
        size_t dq = (size_t)bx * 128 * DK * 2;
        base[0] = (const char*)g_Qh + qo; base[1] = (const char*)g_Qm + qo;
        base[2] = (const char*)g_Ql + qo;
        base[3] = (const char*)g_Dh + dq; base[4] = (const char*)g_Dm + dq;
        base[5] = (const char*)g_Dl + dq;
    }

    const int lrow = tid >> 1, lhalf = tid & 1;
    auto load_stage = [&](int st, int c) {
        size_t goff = (size_t)lrow * (DK * 2) + (size_t)c * 64 + (size_t)lhalf * 32;
        uint32_t soff = sb + st * STAGE_B + lrow * T_PITCH + lhalf * 32;
#pragma unroll
        for (int t = 0; t < 6; t++) {
            const char* gp = base[t] + goff;
            uint32_t    sp = soff + t * TILE_B;
            cp16(sp,      gp);
            cp16(sp + 16, gp + 16);
        }
    };

    float c[4][4][4];
#pragma unroll
    for (int i = 0; i < 4; i++)
#pragma unroll
        for (int j = 0; j < 4; j++)
#pragma unroll
            for (int q = 0; q < 4; q++) c[i][j][q] = 0.0f;

    const int a_row = wm * 64 + (lane & 15);
    const int a_kh  = (lane >> 4) * 8;
    const int b_row = wn * 32 + (lane & 15);
    const int b_kh  = a_kh;

    load_stage(0, 0); CP_COMMIT();
    load_stage(1, 1); CP_COMMIT();

    for (int ch = 0; ch < NCHUNK; ch++) {
        __syncthreads();
        if (ch + 2 < NCHUNK) load_stage((ch + 2) % 3, ch + 2);
        CP_COMMIT();
        CP_WAIT2();
        __syncthreads();

        const uint32_t stg = sb + (ch % 3) * STAGE_B;
#pragma unroll
        for (int kk = 0; kk < 2; kk++) {
            const int k0 = kk * 16;
            uint32_t a[3][4][4], b[3][2][4];
#pragma unroll
            for (int s = 0; s < 3; s++) {
                uint32_t tb = stg + s * TILE_B;
#pragma unroll
                for (int mb = 0; mb < 4; mb++)
                    ldsm4(a[s][mb], tb + (a_row + mb * 16) * T_PITCH + (k0 + a_kh) * 2);
                uint32_t tbb = stg + (3 + s) * TILE_B;
#pragma unroll
                for (int ng = 0; ng < 2; ng++)
                    ldsm4(b[s][ng], tbb + (b_row + ng * 16) * T_PITCH + (k0 + b_kh) * 2);
            }
            const int pa[6] = {0, 0, 1, 1, 0, 2};
            const int pb[6] = {0, 1, 0, 1, 2, 0};
#pragma unroll
            for (int p = 0; p < 6; p++) {
#pragma unroll
                for (int mb = 0; mb < 4; mb++)
#pragma unroll
                    for (int nb = 0; nb < 4; nb++) {
                        const uint32_t* bg = b[pb[p]][nb >> 1];
                        mma16816(c[mb][nb], a[pa[p]][mb], bg[nb & 1], bg[(nb & 1) + 2]);
                    }
            }
        }
    }

    const size_t crow0 = (size_t)by * 128;
    const size_t ccol0 = (size_t)bx * 128;
    const int r_in  = lane >> 2;
    const int c_in  = (lane & 3) * 2;
#pragma unroll
    for (int mb = 0; mb < 4; mb++) {
        size_t row0 = crow0 + wm * 64 + mb * 16 + r_in;
#pragma unroll
        for (int nb = 0; nb < 4; nb++) {
            size_t col = ccol0 + wn * 32 + nb * 8 + c_in;
            *(float2*)(g_sims + row0 * ND + col)       = make_float2(c[mb][nb][0], c[mb][nb][1]);
            *(float2*)(g_sims + (row0 + 8) * ND + col) = make_float2(c[mb][nb][2], c[mb][nb][3]);
        }
    }
}

// ---------------------------------------------------------------------------
// Approx pass: per-row max, sum(exp), adaptive-threshold candidate compaction.
// ---------------------------------------------------------------------------
__global__ __launch_bounds__(256)
void approx_kernel()
{
    extern __shared__ float row[];           // ND floats
    __shared__ float redv[256];
    __shared__ int   redc[256];
    __shared__ float s_m;
    __shared__ int   s_cnt;

    const int r   = blockIdx.x;
    const int tid = threadIdx.x;

    const float4* src  = (const float4*)(g_sims + (size_t)r * ND);
    float4*       drow = (float4*)row;

    float lmax = -INFINITY;
    for (int i = tid; i < ND / 4; i += 256) {
        float4 v = src[i];
        drow[i] = v;
        lmax = fmaxf(lmax, fmaxf(fmaxf(v.x, v.y), fmaxf(v.z, v.w)));
    }
    redv[tid] = lmax;
    __syncthreads();
#pragma unroll
    for (int s = 128; s > 0; s >>= 1) {
        if (tid < s) redv[tid] = fmaxf(redv[tid], redv[tid + s]);
        __syncthreads();
    }
    if (tid == 0) s_m = redv[0];
    __syncthreads();
    const float m = s_m;

    float lsum = 0.0f;
    for (int i = tid; i < ND / 4; i += 256) {
        float4 v = drow[i];
        lsum += expf(v.x - m) + expf(v.y - m) + expf(v.z - m) + expf(v.w - m);
    }
    redv[tid] = lsum;
    __syncthreads();
#pragma unroll
    for (int s = 128; s > 0; s >>= 1) {
        if (tid < s) redv[tid] += redv[tid + s];
        __syncthreads();
    }
    if (tid == 0) {
        g_rowm[r]   = m;
        g_rowsum[r] = redv[0];
    }
    __syncthreads();

    // Adaptive threshold: grow Delta until >=40 entries above m - Delta.
    float Delta = 14.0f;
    int K = 0;
    for (;;) {
        float cth = m - Delta;
        int lc = 0;
        for (int i = tid; i < ND / 4; i += 256) {
            float4 v = drow[i];
            lc += (v.x > cth) + (v.y > cth) + (v.z > cth) + (v.w > cth);
        }
        redc[tid] = lc;
        __syncthreads();
#pragma unroll
        for (int s = 128; s > 0; s >>= 1) {
            if (tid < s) redc[tid] += redc[tid + s];
            __syncthreads();
        }
        K = redc[0];
        __syncthreads();
        if (K >= 40 || Delta > 2000.0f) break;
        Delta += 7.0f;
    }

    // Compact candidate indices
    const float cth = m - Delta;
    if (tid == 0) s_cnt = 0;
    __syncthreads();
    for (int i = tid; i < ND; i += 256) {
        if (row[i] > cth) {
            int s = atomicAdd(&s_cnt, 1);
            if (s < CANDCAP) g_cand[(size_t)r * CANDCAP + s] = i;
        }
    }
    __syncthreads();
    if (tid == 0) g_ncand[r] = s_cnt < CANDCAP ? s_cnt : CANDCAP;
}

// ---------------------------------------------------------------------------
// Exact refine: exact candidate logits (serial ascending-k fmaf chain), exact
// top-20, AND exact-head/approx-tail softmax sum correction:
//   sum = rowsum_ap*exp(m_ap - m_ex) - SUM_cand exp(v_ap - m_ex)
//                                    + SUM_cand exp(v_ex - m_ex)
// ---------------------------------------------------------------------------
__global__ __launch_bounds__(256)
void refine_kernel(const float* __restrict__ Q, const float* __restrict__ Dm,
                   float* __restrict__ out_scores, float* __restrict__ out_inds,
                   float* __restrict__ out_n,      float* __restrict__ out_mask)
{
    __shared__ float qs[DK];
    __shared__ float vals[CANDCAP];
    __shared__ float av[CANDCAP];
    __shared__ int   cidx[CANDCAP];
    __shared__ float redv[256];
    __shared__ float redw[256];
    __shared__ int   redi[256];
    __shared__ float topv[TOPK];
    __shared__ int   topi[TOPK];
    __shared__ float s_mex, s_sum;

    const int r   = blockIdx.x;
    const int tid = threadIdx.x;
    const int K   = g_ncand[r];
    const float m_ap   = g_rowm[r];
    const float sum_ap = g_rowsum[r];

    for (int i = tid; i < DK / 4; i += 256)
        ((float4*)qs)[i] = ((const float4*)(Q + (size_t)r * DK))[i];
    __syncthreads();

    for (int c = tid; c < K; c += 256) {
        int idx = g_cand[(size_t)r * CANDCAP + c];
        const float4* dr = (const float4*)(Dm + (size_t)idx * DK);
        float acc = 0.0f;
#pragma unroll 8
        for (int j = 0; j < DK / 4; j++) {
            float4 q4 = ((const float4*)qs)[j];
            float4 d4 = __ldg(dr + j);
            acc = fmaf(q4.x, d4.x, acc);
            acc = fmaf(q4.y, d4.y, acc);
            acc = fmaf(q4.z, d4.z, acc);
            acc = fmaf(q4.w, d4.w, acc);
        }
        vals[c] = acc;
        av[c]   = __ldg(g_sims + (size_t)r * ND + idx);
        cidx[c] = idx;
    }
    __syncthreads();

    // exact max over candidates (global max is guaranteed a candidate)
    {
        float lm = -INFINITY;
        for (int c = tid; c < K; c += 256) lm = fmaxf(lm, vals[c]);
        redv[tid] = lm;
        __syncthreads();
#pragma unroll
        for (int s = 128; s > 0; s >>= 1) {
            if (tid < s) redv[tid] = fmaxf(redv[tid], redv[tid + s]);
            __syncthreads();
        }
        if (tid == 0) s_mex = redv[0];
        __syncthreads();
    }
    const float m_ex = s_mex;

    // corrected softmax sum: exact head + approx tail
    {
        float le = 0.0f, la = 0.0f;
        for (int c = tid; c < K; c += 256) {
            le += expf(vals[c] - m_ex);
            la += expf(av[c]   - m_ex);
        }
        redv[tid] = le;
        redw[tid] = la;
        __syncthreads();
#pragma unroll
        for (int s = 128; s > 0; s >>= 1) {
            if (tid < s) { redv[tid] += redv[tid + s]; redw[tid] += redw[tid + s]; }
            __syncthreads();
        }
        if (tid == 0)
            s_sum = sum_ap * expf(m_ap - m_ex) - redw[0] + redv[0];
        __syncthreads();
    }
    const float sum = s_sum;

    // exact top-20: 20 block argmax iterations, tie-break lowest index
    for (int it = 0; it < TOPK; it++) {
        float bv = -INFINITY;
        int   bi = ND;
        for (int c = tid; c < K; c += 256) {
            float v = vals[c];
            int   i = cidx[c];
            if (v > bv || (v == bv && i < bi)) { bv = v; bi = i; }
        }
        redv[tid] = bv;
        redi[tid] = bi;
        __syncthreads();
#pragma unroll
        for (int s = 128; s > 0; s >>= 1) {
            if (tid < s) {
                float ov = redv[tid + s];
                int   oi = redi[tid + s];
                if (ov > redv[tid] || (ov == redv[tid] && oi < redi[tid])) {
                    redv[tid] = ov;
                    redi[tid] = oi;
                }
            }
            __syncthreads();
        }
        if (tid == 0) {
            topv[it] = redv[0];
            topi[it] = redi[0];
        }
        __syncthreads();
        for (int c = tid; c < K; c += 256)
            if (cidx[c] == topi[it]) vals[c] = -INFINITY;
        __syncthreads();
    }

    if (tid < TOPK) {
        float sc   = expf(topv[tid] - m_ex) / sum;
        bool  keep = sc > THRESH;
        out_scores[(size_t)r * TOPK + tid] = keep ? sc : 0.0f;
        out_inds  [(size_t)r * TOPK + tid] = (float)topi[tid];
        out_mask  [(size_t)r * TOPK + tid] = keep ? 1.0f : 0.0f;
    }
    if (tid == 0) {
        int cnt = 0;
#pragma unroll
        for (int j = 0; j < TOPK; j++) {
            float sc = expf(topv[j] - m_ex) / sum;
            cnt += (sc > THRESH) ? 1 : 0;
        }
        out_n[r] = (float)cnt;
    }
}

// ---------------------------------------------------------------------------
extern "C" void kernel_launch(void* const* d_in, const int* in_sizes, int n_in,
                              void* d_out, int out_size)
{
    const float* Q = (const float*)d_in[0];
    const float* D = (const float*)d_in[1];
    float* out = (float*)d_out;

    float* out_scores = out;
    float* out_inds   = out + (size_t)NQ * TOPK;
    float* out_n      = out + (size_t)2 * NQ * TOPK;
    float* out_mask   = out + (size_t)2 * NQ * TOPK + NQ;

    cudaFuncSetAttribute(gemm_kernel,
                         cudaFuncAttributeMaxDynamicSharedMemorySize, GEMM_SMEM);
    cudaFuncSetAttribute(approx_kernel,
                         cudaFuncAttributeMaxDynamicSharedMemorySize, ND * (int)sizeof(float));

    split_q<<<(NQ * DK / 2 + 255) / 256, 256>>>(Q);
    split_d<<<(ND * DK / 2 + 255) / 256, 256>>>(D);

    gemm_kernel<<<(NQ / 128) * (ND / 128), 256, GEMM_SMEM>>>();

    approx_kernel<<<NQ, 256, ND * sizeof(float)>>>();

    refine_kernel<<<NQ, 256>>>(Q, D, out_scores, out_inds, out_n, out_mask);

    (void)in_sizes; (void)n_in; (void)out_size;
}